// round 2
// baseline (speedup 1.0000x reference)
#include <cuda_runtime.h>

#define NODES_D 128
#define NMAX 50048   // padded to multiple of 64

// Scratch (no allocations allowed)
__device__ float g_agg[NMAX * NODES_D];
__device__ float g_h1[NMAX * NODES_D];
__device__ float g_h2[NMAX * NODES_D];
__device__ float g_cnt[NMAX];

// ---------------------------------------------------------------------------
// zero kernel (float4 granularity)
// ---------------------------------------------------------------------------
__global__ void zero_k(float4* __restrict__ p, int n4) {
    int i = blockIdx.x * blockDim.x + threadIdx.x;
    if (i < n4) p[i] = make_float4(0.f, 0.f, 0.f, 0.f);
}

// ---------------------------------------------------------------------------
// scatter: one warp per edge. msg = x[src]*w -> red.add into agg[dst]
// optionally counts in-degree (layer 1 only; graph is static per call)
// ---------------------------------------------------------------------------
__global__ void scatter_k(const float* __restrict__ x,
                          const int* __restrict__ src,
                          const int* __restrict__ dst,
                          const float* __restrict__ ew,
                          float* __restrict__ agg,
                          float* __restrict__ cnt,
                          int E, int do_cnt) {
    int e = (blockIdx.x * blockDim.x + threadIdx.x) >> 5;
    int lane = threadIdx.x & 31;
    if (e >= E) return;

    int s = 0, d = 0;
    float w = 0.f;
    if (lane == 0) {
        s = src[e];
        d = dst[e];
        w = ew[e];
    }
    s = __shfl_sync(0xffffffffu, s, 0);
    d = __shfl_sync(0xffffffffu, d, 0);
    w = __shfl_sync(0xffffffffu, w, 0);

    const float4 v = *(const float4*)(x + (size_t)s * NODES_D + lane * 4);
    float mx = v.x * w, my = v.y * w, mz = v.z * w, mw = v.w * w;
    float* p = agg + (size_t)d * NODES_D + lane * 4;
    asm volatile("red.global.add.v4.f32 [%0], {%1,%2,%3,%4};"
                 :: "l"(p), "f"(mx), "f"(my), "f"(mz), "f"(mw) : "memory");

    if (do_cnt && lane == 0) atomicAdd(cnt + d, 1.0f);
}

// ---------------------------------------------------------------------------
// Fused: out = (agg/max(cnt,1)) @ Wl^T + b + xin @ Wr^T
//        then BN(eval)+leaky(0.1)   (FUSE_BN=true, layers 1&2)
//        or  row L2-normalize       (FUSE_BN=false, layer 3)
// Block: 256 threads as 16x16; 64 rows x DOUT cols per block.
// Thread (ty,tx): 4 rows x CPT cols.  K = 256 (concat of mean|x), chunks of 16.
// ---------------------------------------------------------------------------
template <int DOUT, bool FUSE_BN>
__global__ void __launch_bounds__(256)
gemm_fused(const float* __restrict__ agg,
           const float* __restrict__ xin,
           const float* __restrict__ Wl,
           const float* __restrict__ bias,
           const float* __restrict__ Wr,
           const float* __restrict__ bng, const float* __restrict__ bnb,
           const float* __restrict__ bnm, const float* __restrict__ bnv,
           float* __restrict__ out, int n) {
    constexpr int CPT = DOUT / 16;      // cols per thread (8 or 4)
    constexpr int TPO = 256 / DOUT;     // loader threads per output col (2 or 4)
    constexpr int F4PT = 16 / (4 * TPO); // float4 weight loads per thread (2 or 1)

    __shared__ float s_in[64 * 16];
    __shared__ float s_w[16 * DOUT];
    __shared__ float s_inv[64];

    const int tid = threadIdx.x;
    const int ty = tid >> 4, tx = tid & 15;
    const int row0 = blockIdx.x * 64;

    if (tid < 64) {
        int r = row0 + tid;
        float c = (r < n) ? g_cnt[r] : 1.0f;
        s_inv[tid] = 1.0f / fmaxf(c, 1.0f);
    }
    __syncthreads();

    // loader mapping for input tile
    const int lr = tid >> 2;            // 0..63 local row
    const int lk4 = (tid & 3) * 4;      // k offset within chunk
    const int grow = row0 + lr;
    const bool rv = grow < n;
    const float inv = s_inv[lr];

    // loader mapping for weight tile
    const int wo = tid / TPO;           // output col
    const int wsub = tid % TPO;

    float acc[4][CPT];
#pragma unroll
    for (int i = 0; i < 4; ++i)
#pragma unroll
        for (int j = 0; j < CPT; ++j) acc[i][j] = 0.f;

    for (int kc = 0; kc < 256; kc += 16) {
        // ---- load input tile (mean part scaled by 1/cnt) ----
        float4 v = make_float4(0.f, 0.f, 0.f, 0.f);
        if (rv) {
            int k = kc + lk4;
            if (k < 128) {
                v = *(const float4*)(agg + (size_t)grow * 128 + k);
                v.x *= inv; v.y *= inv; v.z *= inv; v.w *= inv;
            } else {
                v = *(const float4*)(xin + (size_t)grow * 128 + (k - 128));
            }
        }
        *(float4*)(s_in + lr * 16 + lk4) = v;

        // ---- load weight tile (transposed into s_w[kk][o]) ----
#pragma unroll
        for (int f = 0; f < F4PT; ++f) {
            int kk = wsub * (16 / TPO) + f * 4;
            int k = kc + kk;
            const float* Wp = (k < 128) ? (Wl + (size_t)wo * 128 + k)
                                        : (Wr + (size_t)wo * 128 + (k - 128));
            float4 wv = *(const float4*)Wp;
            s_w[(kk + 0) * DOUT + wo] = wv.x;
            s_w[(kk + 1) * DOUT + wo] = wv.y;
            s_w[(kk + 2) * DOUT + wo] = wv.z;
            s_w[(kk + 3) * DOUT + wo] = wv.w;
        }
        __syncthreads();

        // ---- compute ----
#pragma unroll
        for (int kk = 0; kk < 16; ++kk) {
            float a0 = s_in[(ty * 4 + 0) * 16 + kk];
            float a1 = s_in[(ty * 4 + 1) * 16 + kk];
            float a2 = s_in[(ty * 4 + 2) * 16 + kk];
            float a3 = s_in[(ty * 4 + 3) * 16 + kk];
#pragma unroll
            for (int j4 = 0; j4 < CPT; j4 += 4) {
                float4 b = *(const float4*)(s_w + kk * DOUT + tx * CPT + j4);
                acc[0][j4 + 0] += a0 * b.x; acc[0][j4 + 1] += a0 * b.y;
                acc[0][j4 + 2] += a0 * b.z; acc[0][j4 + 3] += a0 * b.w;
                acc[1][j4 + 0] += a1 * b.x; acc[1][j4 + 1] += a1 * b.y;
                acc[1][j4 + 2] += a1 * b.z; acc[1][j4 + 3] += a1 * b.w;
                acc[2][j4 + 0] += a2 * b.x; acc[2][j4 + 1] += a2 * b.y;
                acc[2][j4 + 2] += a2 * b.z; acc[2][j4 + 3] += a2 * b.w;
                acc[3][j4 + 0] += a3 * b.x; acc[3][j4 + 1] += a3 * b.y;
                acc[3][j4 + 2] += a3 * b.z; acc[3][j4 + 3] += a3 * b.w;
            }
        }
        __syncthreads();
    }

    // ---- epilogue ----
#pragma unroll
    for (int i = 0; i < 4; ++i) {
        float vals[CPT];
#pragma unroll
        for (int j = 0; j < CPT; ++j) {
            int c = tx * CPT + j;
            float val = acc[i][j] + bias[c];
            if (FUSE_BN) {
                val = (val - bnm[c]) * (bng[c] * rsqrtf(bnv[c] + 1e-5f)) + bnb[c];
                val = (val >= 0.f) ? val : 0.1f * val;
            }
            vals[j] = val;
        }
        if (!FUSE_BN) {
            // L2 row-normalize: reduce over the 16 lanes (same ty) owning this row
            float ss = 0.f;
#pragma unroll
            for (int j = 0; j < CPT; ++j) ss += vals[j] * vals[j];
#pragma unroll
            for (int off = 8; off; off >>= 1)
                ss += __shfl_xor_sync(0xffffffffu, ss, off);
            float scale = 1.0f / fmaxf(sqrtf(ss), 1e-12f);
#pragma unroll
            for (int j = 0; j < CPT; ++j) vals[j] *= scale;
        }
        int r = row0 + ty * 4 + i;
        if (r < n) {
#pragma unroll
            for (int j4 = 0; j4 < CPT; j4 += 4) {
                float4 o;
                o.x = vals[j4 + 0]; o.y = vals[j4 + 1];
                o.z = vals[j4 + 2]; o.w = vals[j4 + 3];
                *(float4*)(out + (size_t)r * DOUT + tx * CPT + j4) = o;
            }
        }
    }
}

// ---------------------------------------------------------------------------
extern "C" void kernel_launch(void* const* d_in, const int* in_sizes, int n_in,
                              void* d_out, int out_size) {
    const float* x    = (const float*)d_in[0];
    const int*   ei   = (const int*)d_in[1];   // int32! (JAX canonicalizes int64->int32)
    const float* ew   = (const float*)d_in[2];
    const float* W1l  = (const float*)d_in[3];
    const float* b1   = (const float*)d_in[4];
    const float* W1r  = (const float*)d_in[5];
    const float* W2l  = (const float*)d_in[6];
    const float* b2   = (const float*)d_in[7];
    const float* W2r  = (const float*)d_in[8];
    const float* W3l  = (const float*)d_in[9];
    const float* b3   = (const float*)d_in[10];
    const float* W3r  = (const float*)d_in[11];
    const float* bn1g = (const float*)d_in[12];
    const float* bn1b = (const float*)d_in[13];
    const float* bn1m = (const float*)d_in[14];
    const float* bn1v = (const float*)d_in[15];
    const float* bn2g = (const float*)d_in[16];
    const float* bn2b = (const float*)d_in[17];
    const float* bn2m = (const float*)d_in[18];
    const float* bn2v = (const float*)d_in[19];

    const int n = in_sizes[0] / NODES_D;
    const int e = in_sizes[2];

    float *agg, *h1, *h2, *cnt;
    cudaGetSymbolAddress((void**)&agg, g_agg);
    cudaGetSymbolAddress((void**)&h1, g_h1);
    cudaGetSymbolAddress((void**)&h2, g_h2);
    cudaGetSymbolAddress((void**)&cnt, g_cnt);

    const int* src = ei;
    const int* dst = ei + e;

    const int nd4 = n * NODES_D / 4;
    const int zb  = (nd4 + 255) / 256;
    const int cn4 = (n + 3) / 4;
    const int czb = (cn4 + 255) / 256;
    const int sb  = (e + 7) / 8;          // 8 warps per 256-thread block
    const int gb  = (n + 63) / 64;

    // Layer 1
    zero_k<<<zb, 256>>>((float4*)agg, nd4);
    zero_k<<<czb, 256>>>((float4*)cnt, cn4);
    scatter_k<<<sb, 256>>>(x, src, dst, ew, agg, cnt, e, 1);
    gemm_fused<128, true><<<gb, 256>>>(agg, x, W1l, b1, W1r,
                                       bn1g, bn1b, bn1m, bn1v, h1, n);
    // Layer 2
    zero_k<<<zb, 256>>>((float4*)agg, nd4);
    scatter_k<<<sb, 256>>>(h1, src, dst, ew, agg, cnt, e, 0);
    gemm_fused<128, true><<<gb, 256>>>(agg, h1, W2l, b2, W2r,
                                       bn2g, bn2b, bn2m, bn2v, h2, n);
    // Layer 3 (+ L2 normalize)
    zero_k<<<zb, 256>>>((float4*)agg, nd4);
    scatter_k<<<sb, 256>>>(h2, src, dst, ew, agg, cnt, e, 0);
    gemm_fused<64, false><<<gb, 256>>>(agg, h2, W3l, b3, W3r,
                                       nullptr, nullptr, nullptr, nullptr,
                                       (float*)d_out, n);
}

// round 3
// speedup vs baseline: 1.0472x; 1.0472x over previous
#include <cuda_runtime.h>

#define NODES_D 128
#define NMAX 50048   // padded to multiple of 128

// Scratch (no allocations allowed)
__device__ float g_agg[NMAX * NODES_D];
__device__ float g_h1[NMAX * NODES_D];
__device__ float g_h2[NMAX * NODES_D];
__device__ float g_cnt[NMAX];

// ---------------------------------------------------------------------------
// zero kernel (float4 granularity)
// ---------------------------------------------------------------------------
__global__ void zero_k(float4* __restrict__ p, int n4) {
    int i = blockIdx.x * blockDim.x + threadIdx.x;
    if (i < n4) p[i] = make_float4(0.f, 0.f, 0.f, 0.f);
}

// ---------------------------------------------------------------------------
// scatter: one warp per edge. msg = x[src]*w -> red.add into agg[dst]
// ---------------------------------------------------------------------------
__global__ void scatter_k(const float* __restrict__ x,
                          const int* __restrict__ src,
                          const int* __restrict__ dst,
                          const float* __restrict__ ew,
                          float* __restrict__ agg,
                          float* __restrict__ cnt,
                          int E, int do_cnt) {
    int e = (blockIdx.x * blockDim.x + threadIdx.x) >> 5;
    int lane = threadIdx.x & 31;
    if (e >= E) return;

    int s = 0, d = 0;
    float w = 0.f;
    if (lane == 0) {
        s = src[e];
        d = dst[e];
        w = ew[e];
    }
    s = __shfl_sync(0xffffffffu, s, 0);
    d = __shfl_sync(0xffffffffu, d, 0);
    w = __shfl_sync(0xffffffffu, w, 0);

    const float4 v = *(const float4*)(x + (size_t)s * NODES_D + lane * 4);
    float mx = v.x * w, my = v.y * w, mz = v.z * w, mw = v.w * w;
    float* p = agg + (size_t)d * NODES_D + lane * 4;
    asm volatile("red.global.add.v4.f32 [%0], {%1,%2,%3,%4};"
                 :: "l"(p), "f"(mx), "f"(my), "f"(mz), "f"(mw) : "memory");

    if (do_cnt && lane == 0) atomicAdd(cnt + d, 1.0f);
}

// ---------------------------------------------------------------------------
// Fused GEMM: out = (agg/max(cnt,1)) @ Wl^T + b + xin @ Wr^T
//   + BN(eval)+leaky(0.1)  (FUSE_BN)  or  row L2-normalize (!FUSE_BN)
//
// Block: 256 threads (ty=tid/16, tx=tid%16). Tile: 128 rows x DOUT cols.
// Thread: 8 rows x CPT cols (CPT = DOUT/16).
// K = 256 (mean | x concat), chunks of 16, A tile stored TRANSPOSED
// (s_a[kk][row]) so both A and B are read with LDS.128:
//   per kk: 2 LDS.128 (A rows) + CPT/4 LDS.128 (B cols) for 8*CPT FMAs.
// ---------------------------------------------------------------------------
template <int DOUT, bool FUSE_BN>
__global__ void __launch_bounds__(256, 2)
gemm_fused(const float* __restrict__ agg,
           const float* __restrict__ xin,
           const float* __restrict__ Wl,
           const float* __restrict__ bias,
           const float* __restrict__ Wr,
           const float* __restrict__ bng, const float* __restrict__ bnb,
           const float* __restrict__ bnm, const float* __restrict__ bnv,
           const float* __restrict__ cnt,
           float* __restrict__ out, int n) {
    constexpr int CPT = DOUT / 16;      // cols per thread (8 or 4)

    __shared__ float s_a[16 * 128];     // [kk][row]
    __shared__ float s_w[16 * DOUT];    // [kk][col]
    __shared__ float s_inv[128];

    const int tid = threadIdx.x;
    const int ty = tid >> 4, tx = tid & 15;
    const int row0 = blockIdx.x * 128;

    if (tid < 128) {
        int r = row0 + tid;
        float c = (r < n) ? cnt[r] : 1.0f;
        s_inv[tid] = 1.0f / fmaxf(c, 1.0f);
    }
    __syncthreads();

    // A-tile loader mapping: 2 float4 per thread per chunk
    const int lr  = tid >> 1;           // 0..127 local row
    const int lk8 = (tid & 1) * 8;      // k offset within chunk (0 or 8)
    const int grow = row0 + lr;
    const bool rv = grow < n;
    const float inv = s_inv[lr];

    float acc[8][CPT];
#pragma unroll
    for (int i = 0; i < 8; ++i)
#pragma unroll
        for (int j = 0; j < CPT; ++j) acc[i][j] = 0.f;

    for (int kc = 0; kc < 256; kc += 16) {
        // ---- load A tile (transposed; mean part scaled by 1/cnt) ----
#pragma unroll
        for (int f = 0; f < 2; ++f) {
            const int kl = lk8 + f * 4;   // local k 0..15
            const int k = kc + kl;
            float4 v = make_float4(0.f, 0.f, 0.f, 0.f);
            if (rv) {
                if (k < 128) {
                    v = *(const float4*)(agg + (size_t)grow * 128 + k);
                    v.x *= inv; v.y *= inv; v.z *= inv; v.w *= inv;
                } else {
                    v = *(const float4*)(xin + (size_t)grow * 128 + (k - 128));
                }
            }
            s_a[(kl + 0) * 128 + lr] = v.x;
            s_a[(kl + 1) * 128 + lr] = v.y;
            s_a[(kl + 2) * 128 + lr] = v.z;
            s_a[(kl + 3) * 128 + lr] = v.w;
        }

        // ---- load W tile (transposed into s_w[kk][col]) ----
        if (DOUT == 128) {
            const int wo  = tid >> 1;
            const int wk8 = (tid & 1) * 8;
#pragma unroll
            for (int f = 0; f < 2; ++f) {
                const int kl = wk8 + f * 4;
                const int k = kc + kl;
                const float* Wp = (k < 128) ? (Wl + (size_t)wo * 128 + k)
                                            : (Wr + (size_t)wo * 128 + (k - 128));
                float4 wv = *(const float4*)Wp;
                s_w[(kl + 0) * DOUT + wo] = wv.x;
                s_w[(kl + 1) * DOUT + wo] = wv.y;
                s_w[(kl + 2) * DOUT + wo] = wv.z;
                s_w[(kl + 3) * DOUT + wo] = wv.w;
            }
        } else {  // DOUT == 64
            const int wo  = tid >> 2;
            const int kl  = (tid & 3) * 4;
            const int k = kc + kl;
            const float* Wp = (k < 128) ? (Wl + (size_t)wo * 128 + k)
                                        : (Wr + (size_t)wo * 128 + (k - 128));
            float4 wv = *(const float4*)Wp;
            s_w[(kl + 0) * DOUT + wo] = wv.x;
            s_w[(kl + 1) * DOUT + wo] = wv.y;
            s_w[(kl + 2) * DOUT + wo] = wv.z;
            s_w[(kl + 3) * DOUT + wo] = wv.w;
        }
        __syncthreads();

        // ---- compute: per kk, 2 LDS.128 (A) + CPT/4 LDS.128 (B), 8*CPT FMA
#pragma unroll
        for (int kk = 0; kk < 16; ++kk) {
            float4 a0 = *(const float4*)(s_a + kk * 128 + ty * 8);
            float4 a1 = *(const float4*)(s_a + kk * 128 + ty * 8 + 4);
            float av[8] = {a0.x, a0.y, a0.z, a0.w, a1.x, a1.y, a1.z, a1.w};
#pragma unroll
            for (int j4 = 0; j4 < CPT; j4 += 4) {
                float4 b = *(const float4*)(s_w + kk * DOUT + tx * CPT + j4);
#pragma unroll
                for (int i = 0; i < 8; ++i) {
                    acc[i][j4 + 0] += av[i] * b.x;
                    acc[i][j4 + 1] += av[i] * b.y;
                    acc[i][j4 + 2] += av[i] * b.z;
                    acc[i][j4 + 3] += av[i] * b.w;
                }
            }
        }
        __syncthreads();
    }

    // ---- epilogue: precompute per-column affine ----
    float mulc[CPT], addc[CPT];
#pragma unroll
    for (int j = 0; j < CPT; ++j) {
        const int c = tx * CPT + j;
        if (FUSE_BN) {
            float s = bng[c] * rsqrtf(bnv[c] + 1e-5f);
            mulc[j] = s;
            addc[j] = (bias[c] - bnm[c]) * s + bnb[c];
        } else {
            mulc[j] = 1.0f;
            addc[j] = bias[c];
        }
    }

#pragma unroll
    for (int i = 0; i < 8; ++i) {
        float vals[CPT];
#pragma unroll
        for (int j = 0; j < CPT; ++j) {
            float val = acc[i][j] * mulc[j] + addc[j];
            if (FUSE_BN) val = (val >= 0.f) ? val : 0.1f * val;
            vals[j] = val;
        }
        if (!FUSE_BN) {
            // L2 row-normalize over the 16 tx lanes owning this row
            float ss = 0.f;
#pragma unroll
            for (int j = 0; j < CPT; ++j) ss += vals[j] * vals[j];
#pragma unroll
            for (int off = 8; off; off >>= 1)
                ss += __shfl_xor_sync(0xffffffffu, ss, off);
            float scale = 1.0f / fmaxf(sqrtf(ss), 1e-12f);
#pragma unroll
            for (int j = 0; j < CPT; ++j) vals[j] *= scale;
        }
        const int r = row0 + ty * 8 + i;
        if (r < n) {
#pragma unroll
            for (int j4 = 0; j4 < CPT; j4 += 4) {
                float4 o;
                o.x = vals[j4 + 0]; o.y = vals[j4 + 1];
                o.z = vals[j4 + 2]; o.w = vals[j4 + 3];
                *(float4*)(out + (size_t)r * DOUT + tx * CPT + j4) = o;
            }
        }
    }
}

// ---------------------------------------------------------------------------
extern "C" void kernel_launch(void* const* d_in, const int* in_sizes, int n_in,
                              void* d_out, int out_size) {
    const float* x    = (const float*)d_in[0];
    const int*   ei   = (const int*)d_in[1];   // int32 (JAX canonicalizes int64)
    const float* ew   = (const float*)d_in[2];
    const float* W1l  = (const float*)d_in[3];
    const float* b1   = (const float*)d_in[4];
    const float* W1r  = (const float*)d_in[5];
    const float* W2l  = (const float*)d_in[6];
    const float* b2   = (const float*)d_in[7];
    const float* W2r  = (const float*)d_in[8];
    const float* W3l  = (const float*)d_in[9];
    const float* b3   = (const float*)d_in[10];
    const float* W3r  = (const float*)d_in[11];
    const float* bn1g = (const float*)d_in[12];
    const float* bn1b = (const float*)d_in[13];
    const float* bn1m = (const float*)d_in[14];
    const float* bn1v = (const float*)d_in[15];
    const float* bn2g = (const float*)d_in[16];
    const float* bn2b = (const float*)d_in[17];
    const float* bn2m = (const float*)d_in[18];
    const float* bn2v = (const float*)d_in[19];

    const int n = in_sizes[0] / NODES_D;
    const int e = in_sizes[2];

    float *agg, *h1, *h2, *cnt;
    cudaGetSymbolAddress((void**)&agg, g_agg);
    cudaGetSymbolAddress((void**)&h1, g_h1);
    cudaGetSymbolAddress((void**)&h2, g_h2);
    cudaGetSymbolAddress((void**)&cnt, g_cnt);

    const int* src = ei;
    const int* dst = ei + e;

    const int nd4 = n * NODES_D / 4;
    const int zb  = (nd4 + 255) / 256;
    const int cn4 = (n + 3) / 4;
    const int czb = (cn4 + 255) / 256;
    const int sb  = (e + 7) / 8;          // 8 warps per 256-thread block
    const int gb  = (n + 127) / 128;

    // Layer 1
    zero_k<<<zb, 256>>>((float4*)agg, nd4);
    zero_k<<<czb, 256>>>((float4*)cnt, cn4);
    scatter_k<<<sb, 256>>>(x, src, dst, ew, agg, cnt, e, 1);
    gemm_fused<128, true><<<gb, 256>>>(agg, x, W1l, b1, W1r,
                                       bn1g, bn1b, bn1m, bn1v, cnt, h1, n);
    // Layer 2
    zero_k<<<zb, 256>>>((float4*)agg, nd4);
    scatter_k<<<sb, 256>>>(h1, src, dst, ew, agg, cnt, e, 0);
    gemm_fused<128, true><<<gb, 256>>>(agg, h1, W2l, b2, W2r,
                                       bn2g, bn2b, bn2m, bn2v, cnt, h2, n);
    // Layer 3 (+ L2 normalize)
    zero_k<<<zb, 256>>>((float4*)agg, nd4);
    scatter_k<<<sb, 256>>>(h2, src, dst, ew, agg, cnt, e, 0);
    gemm_fused<64, false><<<gb, 256>>>(agg, h2, W3l, b3, W3r,
                                       nullptr, nullptr, nullptr, nullptr,
                                       cnt, (float*)d_out, n);
}

// round 4
// speedup vs baseline: 1.7526x; 1.6736x over previous
#include <cuda_runtime.h>
#include <cstdint>

#define NODES_D 128
#define NMAX 50048        // padded to multiple of 128
#define EMAX 800000

// Scratch (no allocations allowed)
__device__ float g_agg[NMAX * NODES_D];   // holds per-layer MEAN aggregate
__device__ float g_h1[NMAX * NODES_D];
__device__ float g_h2[NMAX * NODES_D];
__device__ int   g_cnti[NMAX];
__device__ int   g_rp[NMAX + 1];          // CSR row pointers (by dst)
__device__ int   g_woff[NMAX];            // fill cursors
__device__ int2  g_ep[EMAX];              // packed (src, weight-bits)
__device__ int   g_bsum[64];

// ---------------------------------------------------------------------------
// CSR build kernels
// ---------------------------------------------------------------------------
__global__ void zero_i(int* __restrict__ p, int n) {
    int i = blockIdx.x * blockDim.x + threadIdx.x;
    if (i < n) p[i] = 0;
}

__global__ void count_k(const int* __restrict__ dst, int* __restrict__ cnti, int E) {
    int e = blockIdx.x * blockDim.x + threadIdx.x;
    if (e < E) atomicAdd(&cnti[dst[e]], 1);
}

// per-block (1024 items) exclusive scan -> rp, block totals -> bsum
__global__ void scan1_k(const int* __restrict__ cnt, int* __restrict__ rp,
                        int* __restrict__ bsum, int n) {
    __shared__ int ws[8];
    const int tid = threadIdx.x, lane = tid & 31, wid = tid >> 5;
    const int i0 = blockIdx.x * 1024 + tid * 4;
    int v0 = (i0 + 0 < n) ? cnt[i0 + 0] : 0;
    int v1 = (i0 + 1 < n) ? cnt[i0 + 1] : 0;
    int v2 = (i0 + 2 < n) ? cnt[i0 + 2] : 0;
    int v3 = (i0 + 3 < n) ? cnt[i0 + 3] : 0;
    const int t = v0 + v1 + v2 + v3;
    int p = t;
#pragma unroll
    for (int o = 1; o < 32; o <<= 1) {
        int y = __shfl_up_sync(0xffffffffu, p, o);
        if (lane >= o) p += y;
    }
    if (lane == 31) ws[wid] = p;
    __syncthreads();
    if (wid == 0) {
        int w = (lane < 8) ? ws[lane] : 0;
        int pi = w;
#pragma unroll
        for (int o = 1; o < 8; o <<= 1) {
            int y = __shfl_up_sync(0xffffffffu, pi, o);
            if (lane >= o) pi += y;
        }
        if (lane == 7) bsum[blockIdx.x] = pi;
        if (lane < 8) ws[lane] = pi - w;     // exclusive warp offsets
    }
    __syncthreads();
    const int off = ws[wid] + (p - t);
    if (i0 + 0 < n) rp[i0 + 0] = off;
    if (i0 + 1 < n) rp[i0 + 1] = off + v0;
    if (i0 + 2 < n) rp[i0 + 2] = off + v0 + v1;
    if (i0 + 3 < n) rp[i0 + 3] = off + v0 + v1 + v2;
}

__global__ void scan2_k(int* __restrict__ bsum, int nb) {
    const int lane = threadIdx.x;
    int run = 0;
    for (int base = 0; base < nb; base += 32) {
        int v = (base + lane < nb) ? bsum[base + lane] : 0;
        int p = v;
#pragma unroll
        for (int o = 1; o < 32; o <<= 1) {
            int y = __shfl_up_sync(0xffffffffu, p, o);
            if (lane >= o) p += y;
        }
        if (base + lane < nb) bsum[base + lane] = p - v + run;
        run += __shfl_sync(0xffffffffu, p, 31);
    }
}

__global__ void scan3_k(int* __restrict__ rp, int* __restrict__ woff,
                        const int* __restrict__ bsum, int n, int E) {
    int i = blockIdx.x * blockDim.x + threadIdx.x;
    if (i < n) {
        int v = rp[i] + bsum[i >> 10];
        rp[i] = v;
        woff[i] = v;
    }
    if (i == 0) rp[n] = E;
}

__global__ void fill_k(const int* __restrict__ src, const int* __restrict__ dst,
                       const float* __restrict__ ew, int* __restrict__ woff,
                       int2* __restrict__ ep, int E) {
    int e = blockIdx.x * blockDim.x + threadIdx.x;
    if (e < E) {
        int d = dst[e];
        int p = atomicAdd(&woff[d], 1);
        ep[p] = make_int2(src[e], __float_as_int(ew[e]));
    }
}

// ---------------------------------------------------------------------------
// Pull aggregation: one warp per dst node. out[node] = mean of w*x[src].
// ---------------------------------------------------------------------------
__global__ void __launch_bounds__(256)
gather_k(const float* __restrict__ x, const int* __restrict__ rp,
         const int2* __restrict__ ep, float* __restrict__ out, int n) {
    const int node = (blockIdx.x * blockDim.x + threadIdx.x) >> 5;
    const int lane = threadIdx.x & 31;
    if (node >= n) return;

    const int s0 = rp[node];
    const int s1 = rp[node + 1];
    const float* xb = x + lane * 4;

    float ax = 0.f, ay = 0.f, az = 0.f, aw = 0.f;
    for (int base = s0; base < s1; base += 32) {
        const int m = min(32, s1 - base);
        int2 meta = make_int2(0, 0);
        if (lane < m) meta = ep[base + lane];
        for (int t = 0; t < m; ++t) {
            const int   s = __shfl_sync(0xffffffffu, meta.x, t);
            const float w = __int_as_float(__shfl_sync(0xffffffffu, meta.y, t));
            const float4 v = *(const float4*)(xb + (size_t)s * NODES_D);
            ax += v.x * w; ay += v.y * w; az += v.z * w; aw += v.w * w;
        }
    }
    const float inv = 1.0f / fmaxf((float)(s1 - s0), 1.0f);
    float4 o;
    o.x = ax * inv; o.y = ay * inv; o.z = az * inv; o.w = aw * inv;
    *(float4*)(out + (size_t)node * NODES_D + lane * 4) = o;
}

// ---------------------------------------------------------------------------
// cp.async helpers
// ---------------------------------------------------------------------------
__device__ __forceinline__ void cp16(uint32_t dst, const void* src) {
    asm volatile("cp.async.cg.shared.global [%0], [%1], 16;" :: "r"(dst), "l"(src));
}
__device__ __forceinline__ void cp_commit() {
    asm volatile("cp.async.commit_group;");
}
template <int N>
__device__ __forceinline__ void cp_wait() {
    asm volatile("cp.async.wait_group %0;" :: "n"(N));
}

// ---------------------------------------------------------------------------
// Fused GEMM: out = mean @ Wl^T + b + xin @ Wr^T
//   + BN(eval)+leaky(0.1)  (FUSE_BN)  or  row L2-normalize (!FUSE_BN)
// Tile: 128 rows x DOUT cols, 256 threads (ty=tid/16 rows, tx=tid%16 cols).
// Thread: 8 rows x CPT cols, col mapping c = tx + j*16 (conflict-free LDS).
// K = 256 as 16 chunks of 16, double-buffered via cp.async.
// smem row stride AST=20 floats: 16B aligned AND per-phase conflict-free.
// ---------------------------------------------------------------------------
template <int DOUT, bool FUSE_BN>
__global__ void __launch_bounds__(256, 2)
gemm_fused(const float* __restrict__ agg,      // mean, NMAX-padded
           const float* __restrict__ xin,      // may be unpadded (layer 1)
           const float* __restrict__ Wl,
           const float* __restrict__ bias,
           const float* __restrict__ Wr,
           const float* __restrict__ bng, const float* __restrict__ bnb,
           const float* __restrict__ bnm, const float* __restrict__ bnv,
           float* __restrict__ out, int n) {
    constexpr int CPT = DOUT / 16;
    constexpr int AST = 20;

    __shared__ float s_a[2][128 * AST];
    __shared__ float s_w[2][DOUT * AST];

    const int tid = threadIdx.x;
    const int ty = tid >> 4, tx = tid & 15;
    const int row0 = blockIdx.x * 128;

    // loader mappings
    const int lr0 = tid >> 2;          // A row 0 (0..63); row1 = +64
    const int seg = tid & 3;           // 16B segment within 64B chunk row
    const int segk = seg * 4;
    const bool v0 = (row0 + lr0) < n;
    const bool v1 = (row0 + lr0 + 64) < n;

    uint32_t sa_base[2], sw_base[2];
    sa_base[0] = (uint32_t)__cvta_generic_to_shared(&s_a[0][0]);
    sa_base[1] = (uint32_t)__cvta_generic_to_shared(&s_a[1][0]);
    sw_base[0] = (uint32_t)__cvta_generic_to_shared(&s_w[0][0]);
    sw_base[1] = (uint32_t)__cvta_generic_to_shared(&s_w[1][0]);

    const float4 z4 = make_float4(0.f, 0.f, 0.f, 0.f);

    // issue loads for chunk kc into buffer buf
    auto load_chunk = [&](int buf, int kc) {
        const int koff = (kc & 7) * 16 + segk;
        // ---- A tile ----
        const float* ab = (kc < 8) ? agg : xin;
        const uint32_t da0 = sa_base[buf] + (uint32_t)(lr0 * AST + segk) * 4u;
        const uint32_t da1 = sa_base[buf] + (uint32_t)((lr0 + 64) * AST + segk) * 4u;
        if (v0) cp16(da0, ab + (size_t)(row0 + lr0) * 128 + koff);
        else    *(float4*)&s_a[buf][lr0 * AST + segk] = z4;
        if (v1) cp16(da1, ab + (size_t)(row0 + lr0 + 64) * 128 + koff);
        else    *(float4*)&s_a[buf][(lr0 + 64) * AST + segk] = z4;
        // ---- W tile ----
        const float* wb = (kc < 8) ? Wl : Wr;
        const uint32_t dw0 = sw_base[buf] + (uint32_t)(lr0 * AST + segk) * 4u;
        cp16(dw0, wb + (size_t)lr0 * 128 + koff);
        if (DOUT == 128) {
            const uint32_t dw1 = sw_base[buf] + (uint32_t)((lr0 + 64) * AST + segk) * 4u;
            cp16(dw1, wb + (size_t)(lr0 + 64) * 128 + koff);
        }
    };

    float acc[8][CPT];
#pragma unroll
    for (int i = 0; i < 8; ++i)
#pragma unroll
        for (int j = 0; j < CPT; ++j) acc[i][j] = 0.f;

    load_chunk(0, 0);
    cp_commit();

#pragma unroll 2
    for (int kc = 0; kc < 16; ++kc) {
        const int cur = kc & 1;
        if (kc < 15) {
            load_chunk(cur ^ 1, kc + 1);
            cp_commit();
            cp_wait<1>();
        } else {
            cp_wait<0>();
        }
        __syncthreads();

        const float* sa = s_a[cur];
        const float* sw = s_w[cur];
#pragma unroll
        for (int kk4 = 0; kk4 < 16; kk4 += 4) {
            float4 bv[CPT];
#pragma unroll
            for (int j = 0; j < CPT; ++j)
                bv[j] = *(const float4*)&sw[(tx + j * 16) * AST + kk4];
#pragma unroll
            for (int i = 0; i < 8; ++i) {
                const float4 av = *(const float4*)&sa[(ty * 8 + i) * AST + kk4];
#pragma unroll
                for (int j = 0; j < CPT; ++j) {
                    acc[i][j] += av.x * bv[j].x;
                    acc[i][j] += av.y * bv[j].y;
                    acc[i][j] += av.z * bv[j].z;
                    acc[i][j] += av.w * bv[j].w;
                }
            }
        }
        __syncthreads();
    }

    // ---- epilogue ----
    float mulc[CPT], addc[CPT];
#pragma unroll
    for (int j = 0; j < CPT; ++j) {
        const int c = tx + j * 16;
        if (FUSE_BN) {
            const float s = bng[c] * rsqrtf(bnv[c] + 1e-5f);
            mulc[j] = s;
            addc[j] = (bias[c] - bnm[c]) * s + bnb[c];
        } else {
            mulc[j] = 1.0f;
            addc[j] = bias[c];
        }
    }

#pragma unroll
    for (int i = 0; i < 8; ++i) {
        float vals[CPT];
#pragma unroll
        for (int j = 0; j < CPT; ++j) {
            float val = acc[i][j] * mulc[j] + addc[j];
            if (FUSE_BN) val = (val >= 0.f) ? val : 0.1f * val;
            vals[j] = val;
        }
        if (!FUSE_BN) {
            float ss = 0.f;
#pragma unroll
            for (int j = 0; j < CPT; ++j) ss += vals[j] * vals[j];
#pragma unroll
            for (int off = 8; off; off >>= 1)
                ss += __shfl_xor_sync(0xffffffffu, ss, off);
            const float scale = 1.0f / fmaxf(sqrtf(ss), 1e-12f);
#pragma unroll
            for (int j = 0; j < CPT; ++j) vals[j] *= scale;
        }
        const int r = row0 + ty * 8 + i;
        if (r < n) {
#pragma unroll
            for (int j = 0; j < CPT; ++j)
                out[(size_t)r * DOUT + tx + j * 16] = vals[j];
        }
    }
}

// ---------------------------------------------------------------------------
extern "C" void kernel_launch(void* const* d_in, const int* in_sizes, int n_in,
                              void* d_out, int out_size) {
    const float* x    = (const float*)d_in[0];
    const int*   ei   = (const int*)d_in[1];   // int32 (JAX canonicalizes int64)
    const float* ew   = (const float*)d_in[2];
    const float* W1l  = (const float*)d_in[3];
    const float* b1   = (const float*)d_in[4];
    const float* W1r  = (const float*)d_in[5];
    const float* W2l  = (const float*)d_in[6];
    const float* b2   = (const float*)d_in[7];
    const float* W2r  = (const float*)d_in[8];
    const float* W3l  = (const float*)d_in[9];
    const float* b3   = (const float*)d_in[10];
    const float* W3r  = (const float*)d_in[11];
    const float* bn1g = (const float*)d_in[12];
    const float* bn1b = (const float*)d_in[13];
    const float* bn1m = (const float*)d_in[14];
    const float* bn1v = (const float*)d_in[15];
    const float* bn2g = (const float*)d_in[16];
    const float* bn2b = (const float*)d_in[17];
    const float* bn2m = (const float*)d_in[18];
    const float* bn2v = (const float*)d_in[19];

    const int n = in_sizes[0] / NODES_D;
    const int e = in_sizes[2];

    float *agg, *h1, *h2;
    int *cnti, *rp, *woff, *bsum;
    int2 *ep;
    cudaGetSymbolAddress((void**)&agg, g_agg);
    cudaGetSymbolAddress((void**)&h1, g_h1);
    cudaGetSymbolAddress((void**)&h2, g_h2);
    cudaGetSymbolAddress((void**)&cnti, g_cnti);
    cudaGetSymbolAddress((void**)&rp, g_rp);
    cudaGetSymbolAddress((void**)&woff, g_woff);
    cudaGetSymbolAddress((void**)&bsum, g_bsum);
    cudaGetSymbolAddress((void**)&ep, g_ep);

    const int* src = ei;
    const int* dst = ei + e;

    const int eb = (e + 255) / 256;
    const int nbk = (n + 255) / 256;
    const int nb1024 = (n + 1023) / 1024;
    const int gbk = (n + 7) / 8;          // gather: 8 warps/block
    const int gb = (n + 127) / 128;       // gemm

    // ---- CSR build (per call; graph fixed within call) ----
    zero_i<<<nbk, 256>>>(cnti, n);
    count_k<<<eb, 256>>>(dst, cnti, e);
    scan1_k<<<nb1024, 256>>>(cnti, rp, bsum, n);
    scan2_k<<<1, 32>>>(bsum, nb1024);
    scan3_k<<<nbk, 256>>>(rp, woff, bsum, n, e);
    fill_k<<<eb, 256>>>(src, dst, ew, woff, ep, e);

    // ---- Layer 1 ----
    gather_k<<<gbk, 256>>>(x, rp, ep, agg, n);
    gemm_fused<128, true><<<gb, 256>>>(agg, x, W1l, b1, W1r,
                                       bn1g, bn1b, bn1m, bn1v, h1, n);
    // ---- Layer 2 ----
    gather_k<<<gbk, 256>>>(h1, rp, ep, agg, n);
    gemm_fused<128, true><<<gb, 256>>>(agg, h1, W2l, b2, W2r,
                                       bn2g, bn2b, bn2m, bn2v, h2, n);
    // ---- Layer 3 (+ L2 normalize) ----
    gather_k<<<gbk, 256>>>(h2, rp, ep, agg, n);
    gemm_fused<64, false><<<gb, 256>>>(agg, h2, W3l, b3, W3r,
                                       nullptr, nullptr, nullptr, nullptr,
                                       (float*)d_out, n);
}

// round 6
// speedup vs baseline: 2.3340x; 1.3317x over previous
#include <cuda_runtime.h>
#include <cuda_bf16.h>
#include <cstdint>

#define NODES_D 128
#define NMAX 50048        // padded to multiple of 256
#define EMAX 800000

// Scratch (no allocations allowed)
__device__ float g_agg[NMAX * NODES_D];   // per-layer MEAN aggregate
__device__ float g_h1[NMAX * NODES_D];
__device__ float g_h2[NMAX * NODES_D];
__device__ int   g_cnti[NMAX];
__device__ int   g_rp[NMAX + 1];
__device__ int   g_woff[NMAX];
__device__ int2  g_ep[EMAX];
__device__ int   g_bsum[64];

// ===========================================================================
// helpers
// ===========================================================================
__device__ __forceinline__ uint32_t smem_u32(const void* p) {
    uint32_t a;
    asm("{ .reg .u64 t; cvta.to.shared.u64 t, %1; cvt.u32.u64 %0, t; }"
        : "=r"(a) : "l"(p));
    return a;
}

__device__ __forceinline__ void ldm_x4(uint32_t* r, uint32_t addr) {
    asm volatile("ldmatrix.sync.aligned.m8n8.x4.shared.b16 {%0,%1,%2,%3}, [%4];"
                 : "=r"(r[0]), "=r"(r[1]), "=r"(r[2]), "=r"(r[3]) : "r"(addr));
}

__device__ __forceinline__ void mma_bf16(float* d, const uint32_t* a,
                                         const uint32_t* b) {
    asm volatile(
        "mma.sync.aligned.m16n8k16.row.col.f32.bf16.bf16.f32 "
        "{%0,%1,%2,%3}, {%4,%5,%6,%7}, {%8,%9}, {%0,%1,%2,%3};"
        : "+f"(d[0]), "+f"(d[1]), "+f"(d[2]), "+f"(d[3])
        : "r"(a[0]), "r"(a[1]), "r"(a[2]), "r"(a[3]), "r"(b[0]), "r"(b[1]));
}

__device__ __forceinline__ uint32_t pack2(__nv_bfloat16 a, __nv_bfloat16 b) {
    return (uint32_t)__bfloat16_as_ushort(a) |
           ((uint32_t)__bfloat16_as_ushort(b) << 16);
}

// ===========================================================================
// CSR build kernels
// ===========================================================================
__global__ void zero_i(int* __restrict__ p, int n) {
    int i = blockIdx.x * blockDim.x + threadIdx.x;
    if (i < n) p[i] = 0;
}

__global__ void count_k(const int* __restrict__ dst, int* __restrict__ cnti, int E) {
    int e = blockIdx.x * blockDim.x + threadIdx.x;
    if (e < E) atomicAdd(&cnti[dst[e]], 1);
}

__global__ void scan1_k(const int* __restrict__ cnt, int* __restrict__ rp,
                        int* __restrict__ bsum, int n) {
    __shared__ int ws[8];
    const int tid = threadIdx.x, lane = tid & 31, wid = tid >> 5;
    const int i0 = blockIdx.x * 1024 + tid * 4;
    int v0 = (i0 + 0 < n) ? cnt[i0 + 0] : 0;
    int v1 = (i0 + 1 < n) ? cnt[i0 + 1] : 0;
    int v2 = (i0 + 2 < n) ? cnt[i0 + 2] : 0;
    int v3 = (i0 + 3 < n) ? cnt[i0 + 3] : 0;
    const int t = v0 + v1 + v2 + v3;
    int p = t;
#pragma unroll
    for (int o = 1; o < 32; o <<= 1) {
        int y = __shfl_up_sync(0xffffffffu, p, o);
        if (lane >= o) p += y;
    }
    if (lane == 31) ws[wid] = p;
    __syncthreads();
    if (wid == 0) {
        int w = (lane < 8) ? ws[lane] : 0;
        int pi = w;
#pragma unroll
        for (int o = 1; o < 8; o <<= 1) {
            int y = __shfl_up_sync(0xffffffffu, pi, o);
            if (lane >= o) pi += y;
        }
        if (lane == 7) bsum[blockIdx.x] = pi;
        if (lane < 8) ws[lane] = pi - w;
    }
    __syncthreads();
    const int off = ws[wid] + (p - t);
    if (i0 + 0 < n) rp[i0 + 0] = off;
    if (i0 + 1 < n) rp[i0 + 1] = off + v0;
    if (i0 + 2 < n) rp[i0 + 2] = off + v0 + v1;
    if (i0 + 3 < n) rp[i0 + 3] = off + v0 + v1 + v2;
}

__global__ void scan2_k(int* __restrict__ bsum, int nb) {
    const int lane = threadIdx.x;
    int run = 0;
    for (int base = 0; base < nb; base += 32) {
        int v = (base + lane < nb) ? bsum[base + lane] : 0;
        int p = v;
#pragma unroll
        for (int o = 1; o < 32; o <<= 1) {
            int y = __shfl_up_sync(0xffffffffu, p, o);
            if (lane >= o) p += y;
        }
        if (base + lane < nb) bsum[base + lane] = p - v + run;
        run += __shfl_sync(0xffffffffu, p, 31);
    }
}

__global__ void scan3_k(int* __restrict__ rp, int* __restrict__ woff,
                        const int* __restrict__ bsum, int n, int E) {
    int i = blockIdx.x * blockDim.x + threadIdx.x;
    if (i < n) {
        int v = rp[i] + bsum[i >> 10];
        rp[i] = v;
        woff[i] = v;
    }
    if (i == 0) rp[n] = E;
}

__global__ void fill_k(const int* __restrict__ src, const int* __restrict__ dst,
                       const float* __restrict__ ew, int* __restrict__ woff,
                       int2* __restrict__ ep, int E) {
    int e = blockIdx.x * blockDim.x + threadIdx.x;
    if (e < E) {
        int d = dst[e];
        int p = atomicAdd(&woff[d], 1);
        ep[p] = make_int2(src[e], __float_as_int(ew[e]));
    }
}

// ===========================================================================
// Pull aggregation: one warp per dst node. out[node] = mean of w*x[src].
// ===========================================================================
__global__ void __launch_bounds__(256)
gather_k(const float* __restrict__ x, const int* __restrict__ rp,
         const int2* __restrict__ ep, float* __restrict__ out, int n) {
    const int node = (blockIdx.x * blockDim.x + threadIdx.x) >> 5;
    const int lane = threadIdx.x & 31;
    if (node >= n) return;

    const int s0 = rp[node];
    const int s1 = rp[node + 1];
    const float* xb = x + lane * 4;

    float ax = 0.f, ay = 0.f, az = 0.f, aw = 0.f;
    for (int base = s0; base < s1; base += 32) {
        const int m = min(32, s1 - base);
        int2 meta = make_int2(0, 0);
        if (lane < m) meta = ep[base + lane];
        for (int t = 0; t < m; ++t) {
            const int   s = __shfl_sync(0xffffffffu, meta.x, t);
            const float w = __int_as_float(__shfl_sync(0xffffffffu, meta.y, t));
            const float4 v = *(const float4*)(xb + (size_t)s * NODES_D);
            ax += v.x * w; ay += v.y * w; az += v.z * w; aw += v.w * w;
        }
    }
    const float inv = 1.0f / fmaxf((float)(s1 - s0), 1.0f);
    float4 o;
    o.x = ax * inv; o.y = ay * inv; o.z = az * inv; o.w = aw * inv;
    *(float4*)(out + (size_t)node * NODES_D + lane * 4) = o;
}

// ===========================================================================
// HMMA GEMM: out = [mean|xin](K=256) @ [Wl|Wr]^T + bias, then BN+leaky
// (FUSE_BN) or row L2-normalize (!FUSE_BN).
// bf16 hi/lo Dekker split: a*w ~= ahi*whi + alo*whi + ahi*wlo (fp32 acc).
// Block: 8 warps. FUSE_BN: 128x128 tile, warps 4x2 (32x64 each).
//        !FUSE_BN: 256x64 tile, warps 8x1 (32x64 each, full rows -> easy norm).
// K in 8 chunks of 32: fp32 -> bf16 hi/lo staged in smem (row stride 80B,
// conflict-free for ldmatrix), ldmatrix.x4 fragments, mma.sync m16n8k16.
// ===========================================================================
template <int DOUT, bool FUSE_BN>
__global__ void __launch_bounds__(256)
gemm_mma(const float* __restrict__ agg, const float* __restrict__ xin,
         const float* __restrict__ Wl, const float* __restrict__ bias,
         const float* __restrict__ Wr,
         const float* __restrict__ bng, const float* __restrict__ bnb,
         const float* __restrict__ bnm, const float* __restrict__ bnv,
         float* __restrict__ out, int n) {
    constexpr int BROWS = FUSE_BN ? 128 : 256;
    constexpr int STRIDE = 80;                      // bytes per 32-col bf16 row
    constexpr int OFF_ALO = BROWS * STRIDE;
    constexpr int OFF_WHI = 2 * BROWS * STRIDE;
    constexpr int OFF_WLO = OFF_WHI + DOUT * STRIDE;
    constexpr int OFF_MUL = OFF_WLO + DOUT * STRIDE;
    constexpr int OFF_ADD = OFF_MUL + DOUT * 4;
    constexpr int AIT = BROWS * 8 / 256;            // A float4 loads per thread
    constexpr int WIT = DOUT * 8 / 256;             // W float4 loads per thread

    extern __shared__ char smem[];
    const uint32_t sbase = smem_u32(smem);
    float* s_mul = (float*)(smem + OFF_MUL);
    float* s_add = (float*)(smem + OFF_ADD);

    const int tid = threadIdx.x;
    const int wid = tid >> 5;
    const int lane = tid & 31;
    const int row0 = blockIdx.x * BROWS;

    if (tid < DOUT) {
        if (FUSE_BN) {
            float s = bng[tid] * rsqrtf(bnv[tid] + 1e-5f);
            s_mul[tid] = s;
            s_add[tid] = (bias[tid] - bnm[tid]) * s + bnb[tid];
        } else {
            s_add[tid] = bias[tid];
        }
    }

    // warp tile origin
    const int mrow0 = FUSE_BN ? (wid & 3) * 32 : wid * 32;
    const int ncol0 = FUSE_BN ? (wid >> 2) * 64 : 0;

    // ldmatrix per-lane base offsets
    const int sel = lane >> 3;       // which 8x8 matrix this lane addresses
    const int lr8 = lane & 7;
    uint32_t aOff[2], bOff[4];
#pragma unroll
    for (int m = 0; m < 2; ++m)
        aOff[m] = (uint32_t)((mrow0 + m * 16 + (sel & 1) * 8 + lr8) * STRIDE +
                             (sel >> 1) * 16);
#pragma unroll
    for (int g = 0; g < 4; ++g)
        bOff[g] = (uint32_t)((ncol0 + g * 16 + (sel >> 1) * 8 + lr8) * STRIDE +
                             (sel & 1) * 16);

    float acc[2][8][4];
#pragma unroll
    for (int m = 0; m < 2; ++m)
#pragma unroll
        for (int g = 0; g < 8; ++g)
#pragma unroll
            for (int q = 0; q < 4; ++q) acc[m][g][q] = 0.f;

    for (int ch = 0; ch < 8; ++ch) {
        const float* ab = (ch < 4) ? agg : Wl ? xin : xin;  // keep simple below
        const float* aB = (ch < 4) ? agg : xin;
        const float* wB = (ch < 4) ? Wl : Wr;
        (void)ab;
        const int col0 = (ch & 3) * 32;

        __syncthreads();   // previous iteration's ldmatrix reads done

        // ---- stage A chunk (hi/lo bf16) ----
#pragma unroll
        for (int i = 0; i < AIT; ++i) {
            const int idx = tid + i * 256;
            const int r = idx >> 3;
            const int c4 = (idx & 7) * 4;
            float4 v = make_float4(0.f, 0.f, 0.f, 0.f);
            if (row0 + r < n)
                v = *(const float4*)(aB + (size_t)(row0 + r) * 128 + col0 + c4);
            __nv_bfloat16 hx = __float2bfloat16(v.x);
            __nv_bfloat16 hy = __float2bfloat16(v.y);
            __nv_bfloat16 hz = __float2bfloat16(v.z);
            __nv_bfloat16 hw = __float2bfloat16(v.w);
            uint2 hp = make_uint2(pack2(hx, hy), pack2(hz, hw));
            uint2 lp = make_uint2(
                pack2(__float2bfloat16(v.x - __bfloat162float(hx)),
                      __float2bfloat16(v.y - __bfloat162float(hy))),
                pack2(__float2bfloat16(v.z - __bfloat162float(hz)),
                      __float2bfloat16(v.w - __bfloat162float(hw))));
            const int off = r * STRIDE + c4 * 2;
            *(uint2*)(smem + off) = hp;
            *(uint2*)(smem + OFF_ALO + off) = lp;
        }
        // ---- stage W chunk (hi/lo bf16) ----
#pragma unroll
        for (int i = 0; i < WIT; ++i) {
            const int idx = tid + i * 256;
            const int r = idx >> 3;
            const int c4 = (idx & 7) * 4;
            float4 v = *(const float4*)(wB + (size_t)r * 128 + col0 + c4);
            __nv_bfloat16 hx = __float2bfloat16(v.x);
            __nv_bfloat16 hy = __float2bfloat16(v.y);
            __nv_bfloat16 hz = __float2bfloat16(v.z);
            __nv_bfloat16 hw = __float2bfloat16(v.w);
            uint2 hp = make_uint2(pack2(hx, hy), pack2(hz, hw));
            uint2 lp = make_uint2(
                pack2(__float2bfloat16(v.x - __bfloat162float(hx)),
                      __float2bfloat16(v.y - __bfloat162float(hy))),
                pack2(__float2bfloat16(v.z - __bfloat162float(hz)),
                      __float2bfloat16(v.w - __bfloat162float(hw))));
            const int off = r * STRIDE + c4 * 2;
            *(uint2*)(smem + OFF_WHI + off) = hp;
            *(uint2*)(smem + OFF_WLO + off) = lp;
        }
        __syncthreads();

        // ---- compute: 2 k16 steps per chunk ----
#pragma unroll
        for (int kk = 0; kk < 2; ++kk) {
            const uint32_t kb = kk * 32;     // 16 cols * 2B
            uint32_t ah[2][4], al[2][4];
            ldm_x4(ah[0], sbase + aOff[0] + kb);
            ldm_x4(al[0], sbase + OFF_ALO + aOff[0] + kb);
            ldm_x4(ah[1], sbase + aOff[1] + kb);
            ldm_x4(al[1], sbase + OFF_ALO + aOff[1] + kb);
#pragma unroll
            for (int g = 0; g < 4; ++g) {
                uint32_t bh[4], bl[4];
                ldm_x4(bh, sbase + OFF_WHI + bOff[g] + kb);
                ldm_x4(bl, sbase + OFF_WLO + bOff[g] + kb);
#pragma unroll
                for (int m = 0; m < 2; ++m) {
                    mma_bf16(acc[m][g * 2],     ah[m], bh);
                    mma_bf16(acc[m][g * 2],     al[m], bh);
                    mma_bf16(acc[m][g * 2],     ah[m], bl);
                    mma_bf16(acc[m][g * 2 + 1], ah[m], bh + 2);
                    mma_bf16(acc[m][g * 2 + 1], al[m], bh + 2);
                    mma_bf16(acc[m][g * 2 + 1], ah[m], bl + 2);
                }
            }
        }
    }

    // ---- epilogue ----
    const int qrow = lane >> 2;          // 0..7
    const int qcol = (lane & 3) * 2;
    if (FUSE_BN) {
#pragma unroll
        for (int m = 0; m < 2; ++m) {
            const int rA = row0 + mrow0 + m * 16 + qrow;
            const int rB = rA + 8;
#pragma unroll
            for (int g = 0; g < 8; ++g) {
                const int c0 = ncol0 + g * 8 + qcol;
                const float m0 = s_mul[c0], m1 = s_mul[c0 + 1];
                const float a0 = s_add[c0], a1 = s_add[c0 + 1];
                if (rA < n) {
                    float f0 = acc[m][g][0] * m0 + a0;
                    float f1 = acc[m][g][1] * m1 + a1;
                    float2 o;
                    o.x = (f0 >= 0.f) ? f0 : 0.1f * f0;
                    o.y = (f1 >= 0.f) ? f1 : 0.1f * f1;
                    *(float2*)(out + (size_t)rA * DOUT + c0) = o;
                }
                if (rB < n) {
                    float f2 = acc[m][g][2] * m0 + a0;
                    float f3 = acc[m][g][3] * m1 + a1;
                    float2 o;
                    o.x = (f2 >= 0.f) ? f2 : 0.1f * f2;
                    o.y = (f3 >= 0.f) ? f3 : 0.1f * f3;
                    *(float2*)(out + (size_t)rB * DOUT + c0) = o;
                }
            }
        }
    } else {
#pragma unroll
        for (int m = 0; m < 2; ++m) {
            float ssA = 0.f, ssB = 0.f;
#pragma unroll
            for (int g = 0; g < 8; ++g) {
                const int c0 = g * 8 + qcol;
                const float a0 = s_add[c0], a1 = s_add[c0 + 1];
                float f0 = acc[m][g][0] + a0, f1 = acc[m][g][1] + a1;
                float f2 = acc[m][g][2] + a0, f3 = acc[m][g][3] + a1;
                ssA += f0 * f0 + f1 * f1;
                ssB += f2 * f2 + f3 * f3;
            }
            ssA += __shfl_xor_sync(0xffffffffu, ssA, 1);
            ssA += __shfl_xor_sync(0xffffffffu, ssA, 2);
            ssB += __shfl_xor_sync(0xffffffffu, ssB, 1);
            ssB += __shfl_xor_sync(0xffffffffu, ssB, 2);
            const float scA = 1.0f / fmaxf(sqrtf(ssA), 1e-12f);
            const float scB = 1.0f / fmaxf(sqrtf(ssB), 1e-12f);
            const int rA = row0 + mrow0 + m * 16 + qrow;
            const int rB = rA + 8;
#pragma unroll
            for (int g = 0; g < 8; ++g) {
                const int c0 = g * 8 + qcol;
                const float a0 = s_add[c0], a1 = s_add[c0 + 1];
                if (rA < n) {
                    float2 o;
                    o.x = (acc[m][g][0] + a0) * scA;
                    o.y = (acc[m][g][1] + a1) * scA;
                    *(float2*)(out + (size_t)rA * 64 + c0) = o;
                }
                if (rB < n) {
                    float2 o;
                    o.x = (acc[m][g][2] + a0) * scB;
                    o.y = (acc[m][g][3] + a1) * scB;
                    *(float2*)(out + (size_t)rB * 64 + c0) = o;
                }
            }
        }
    }
}

// smem totals
#define SMEM_G1 (2 * 128 * 80 + 2 * 128 * 80 + 128 * 4 * 2)   // 41984
#define SMEM_G3 (2 * 256 * 80 + 2 * 64 * 80 + 64 * 4 * 2)     // 51712

// ===========================================================================
extern "C" void kernel_launch(void* const* d_in, const int* in_sizes, int n_in,
                              void* d_out, int out_size) {
    const float* x    = (const float*)d_in[0];
    const int*   ei   = (const int*)d_in[1];   // int32 (JAX canonicalizes int64)
    const float* ew   = (const float*)d_in[2];
    const float* W1l  = (const float*)d_in[3];
    const float* b1   = (const float*)d_in[4];
    const float* W1r  = (const float*)d_in[5];
    const float* W2l  = (const float*)d_in[6];
    const float* b2   = (const float*)d_in[7];
    const float* W2r  = (const float*)d_in[8];
    const float* W3l  = (const float*)d_in[9];
    const float* b3   = (const float*)d_in[10];
    const float* W3r  = (const float*)d_in[11];
    const float* bn1g = (const float*)d_in[12];
    const float* bn1b = (const float*)d_in[13];
    const float* bn1m = (const float*)d_in[14];
    const float* bn1v = (const float*)d_in[15];
    const float* bn2g = (const float*)d_in[16];
    const float* bn2b = (const float*)d_in[17];
    const float* bn2m = (const float*)d_in[18];
    const float* bn2v = (const float*)d_in[19];

    const int n = in_sizes[0] / NODES_D;
    const int e = in_sizes[2];

    float *agg, *h1, *h2;
    int *cnti, *rp, *woff, *bsum;
    int2 *ep;
    cudaGetSymbolAddress((void**)&agg, g_agg);
    cudaGetSymbolAddress((void**)&h1, g_h1);
    cudaGetSymbolAddress((void**)&h2, g_h2);
    cudaGetSymbolAddress((void**)&cnti, g_cnti);
    cudaGetSymbolAddress((void**)&rp, g_rp);
    cudaGetSymbolAddress((void**)&woff, g_woff);
    cudaGetSymbolAddress((void**)&bsum, g_bsum);
    cudaGetSymbolAddress((void**)&ep, g_ep);

    cudaFuncSetAttribute(gemm_mma<128, true>,
                         cudaFuncAttributeMaxDynamicSharedMemorySize, SMEM_G1);
    cudaFuncSetAttribute(gemm_mma<64, false>,
                         cudaFuncAttributeMaxDynamicSharedMemorySize, SMEM_G3);

    const int* src = ei;
    const int* dst = ei + e;

    const int eb = (e + 255) / 256;
    const int nbk = (n + 255) / 256;
    const int nb1024 = (n + 1023) / 1024;
    const int gbk = (n + 7) / 8;            // gather: 8 warps/block
    const int gb1 = (n + 127) / 128;        // gemm layers 1,2
    const int gb3 = (n + 255) / 256;        // gemm layer 3

    // ---- CSR build ----
    zero_i<<<nbk, 256>>>(cnti, n);
    count_k<<<eb, 256>>>(dst, cnti, e);
    scan1_k<<<nb1024, 256>>>(cnti, rp, bsum, n);
    scan2_k<<<1, 32>>>(bsum, nb1024);
    scan3_k<<<nbk, 256>>>(rp, woff, bsum, n, e);
    fill_k<<<eb, 256>>>(src, dst, ew, woff, ep, e);

    // ---- Layer 1 ----
    gather_k<<<gbk, 256>>>(x, rp, ep, agg, n);
    gemm_mma<128, true><<<gb1, 256, SMEM_G1>>>(agg, x, W1l, b1, W1r,
                                               bn1g, bn1b, bn1m, bn1v, h1, n);
    // ---- Layer 2 ----
    gather_k<<<gbk, 256>>>(h1, rp, ep, agg, n);
    gemm_mma<128, true><<<gb1, 256, SMEM_G1>>>(agg, h1, W2l, b2, W2r,
                                               bn2g, bn2b, bn2m, bn2v, h2, n);
    // ---- Layer 3 (+ L2 normalize) ----
    gather_k<<<gbk, 256>>>(h2, rp, ep, agg, n);
    gemm_mma<64, false><<<gb3, 256, SMEM_G3>>>(agg, h2, W3l, b3, W3r,
                                               nullptr, nullptr, nullptr, nullptr,
                                               (float*)d_out, n);
}